// round 3
// baseline (speedup 1.0000x reference)
#include <cuda_runtime.h>
#include <cuda_bf16.h>
#include <cstdint>
#include <math.h>

#define BATCH   4096
#define INPUT   1024
#define HIDDEN  2048
#define FANIN   3072   // INPUT + HIDDEN
#define NTOT    4096   // 2 * HIDDEN (mod/tgt interleaved)

// ---------------- scratch (static device globals; no runtime allocation) ----------
static __device__ __nv_bfloat16 g_Ah[(size_t)BATCH * FANIN];
static __device__ __nv_bfloat16 g_Al[(size_t)BATCH * FANIN];
static __device__ __nv_bfloat16 g_Bh[(size_t)NTOT  * FANIN];
static __device__ __nv_bfloat16 g_Bl[(size_t)NTOT  * FANIN];

// ---------------- conversion kernels ----------------------------------------------
// A = [x | h] rows, split into bf16 hi + lo. K-major [BATCH, FANIN].
__global__ void build_A_kernel(const float* __restrict__ xin, const float* __restrict__ hin) {
    size_t i = (size_t)blockIdx.x * blockDim.x + threadIdx.x;
    if (i >= (size_t)BATCH * FANIN / 4) return;
    size_t e = i * 4;
    int r = (int)(e / FANIN);
    int c = (int)(e % FANIN);
    float4 v = (c < INPUT)
        ? *(const float4*)(xin + (size_t)r * INPUT + c)
        : *(const float4*)(hin + (size_t)r * HIDDEN + (c - INPUT));
    float vv[4] = {v.x, v.y, v.z, v.w};
    unsigned short hb[4], lb[4];
#pragma unroll
    for (int q = 0; q < 4; q++) {
        __nv_bfloat16 hi = __float2bfloat16(vv[q]);
        float res = vv[q] - __bfloat162float(hi);
        hb[q] = __bfloat16_as_ushort(hi);
        lb[q] = __bfloat16_as_ushort(__float2bfloat16(res));
    }
    *(ushort4*)((unsigned short*)g_Ah + e) = make_ushort4(hb[0], hb[1], hb[2], hb[3]);
    *(ushort4*)((unsigned short*)g_Al + e) = make_ushort4(lb[0], lb[1], lb[2], lb[3]);
}

// B[n][k] = (n even ? W_mod : W_tgt)[k][n>>1], split hi/lo. Transpose via SMEM tiles.
__global__ void build_B_kernel(const float* __restrict__ Wmod, const float* __restrict__ Wtgt) {
    __shared__ float tile[32][33];
    const float* W = blockIdx.z ? Wtgt : Wmod;
    int k0 = blockIdx.x * 32, j0 = blockIdx.y * 32;
    int tx = threadIdx.x, ty = threadIdx.y;   // 32 x 8
#pragma unroll
    for (int r = ty; r < 32; r += 8)
        tile[r][tx] = W[(size_t)(k0 + r) * HIDDEN + j0 + tx];
    __syncthreads();
#pragma unroll
    for (int jj = ty; jj < 32; jj += 8) {
        float v = tile[tx][jj];              // [k_local][j_local]
        int n = 2 * (j0 + jj) + blockIdx.z;  // interleave mod/tgt
        __nv_bfloat16 hi = __float2bfloat16(v);
        float res = v - __bfloat162float(hi);
        size_t o = (size_t)n * FANIN + k0 + tx;
        g_Bh[o] = hi;
        g_Bl[o] = __float2bfloat16(res);
    }
}

// ---------------- fused GEMM + LTC epilogue (mma.sync path, sm_100 baseline) ------
constexpr int TM = 128, TN = 128, KC = 64;
constexpr int NSTAGE = 4;
constexpr int KTILES = FANIN / KC;          // 48
constexpr int ITERS  = 3 * KTILES;          // 144 (3 split passes)
constexpr int LDROW  = 144;                 // 128B data + 16B pad per row
constexpr int TILE_B = 128 * LDROW;         // 18432 bytes per (A or B) tile
constexpr int STAGE_B = 2 * TILE_B;         // 36864
constexpr int SMEM_BYTES = NSTAGE * STAGE_B; // 147456

__device__ __forceinline__ uint32_t smem_u32(const void* p) {
    uint32_t a;
    asm("{ .reg .u64 t; cvta.to.shared.u64 t, %1; cvt.u32.u64 %0, t; }" : "=r"(a) : "l"(p));
    return a;
}

__device__ __forceinline__ void cp_async16(uint32_t dst, const void* src) {
    asm volatile("cp.async.cg.shared.global [%0], [%1], 16;" :: "r"(dst), "l"(src));
}
__device__ __forceinline__ void cp_commit() {
    asm volatile("cp.async.commit_group;" ::: "memory");
}
template<int N> __device__ __forceinline__ void cp_wait() {
    asm volatile("cp.async.wait_group %0;" :: "n"(N) : "memory");
}
__device__ __forceinline__ void ldsm_x4(uint32_t* r, uint32_t addr) {
    asm volatile("ldmatrix.sync.aligned.m8n8.x4.shared.b16 {%0,%1,%2,%3}, [%4];"
                 : "=r"(r[0]), "=r"(r[1]), "=r"(r[2]), "=r"(r[3]) : "r"(addr));
}
__device__ __forceinline__ void mma_16816(float* c, const uint32_t* a, uint32_t b0, uint32_t b1) {
    asm volatile("mma.sync.aligned.m16n8k16.row.col.f32.bf16.bf16.f32 "
                 "{%0,%1,%2,%3}, {%4,%5,%6,%7}, {%8,%9}, {%0,%1,%2,%3};"
                 : "+f"(c[0]), "+f"(c[1]), "+f"(c[2]), "+f"(c[3])
                 : "r"(a[0]), "r"(a[1]), "r"(a[2]), "r"(a[3]), "r"(b0), "r"(b1));
}

__device__ __forceinline__ void load_stage(uint32_t sm, int stage, int it,
                                           int m0, int n0, int tid)
{
    const __nv_bfloat16* Ap = (it < 2 * KTILES) ? g_Ah : g_Al;                 // p0,p1: Ah ; p2: Al
    const __nv_bfloat16* Bp = (it >= KTILES && it < 2 * KTILES) ? g_Bl : g_Bh; // p1: Bl ; p0,p2: Bh
    int k0 = (it % KTILES) * KC;
    uint32_t sA = sm + stage * STAGE_B;
    uint32_t sB = sA + TILE_B;
#pragma unroll
    for (int i = 0; i < 4; i++) {             // A: 128 rows x 8 chunks = 1024 / 256 thr
        int c = tid + i * 256;
        int row = c >> 3, c16 = c & 7;
        cp_async16(sA + row * LDROW + c16 * 16,
                   Ap + (size_t)(m0 + row) * FANIN + k0 + c16 * 8);
    }
#pragma unroll
    for (int i = 0; i < 4; i++) {             // B: 128 rows x 8 chunks
        int c = tid + i * 256;
        int row = c >> 3, c16 = c & 7;
        cp_async16(sB + row * LDROW + c16 * 16,
                   Bp + (size_t)(n0 + row) * FANIN + k0 + c16 * 8);
    }
}

__global__ void __launch_bounds__(256, 1) ltc_gemm_kernel(
    const float* __restrict__ hp, const float* __restrict__ td,
    const float* __restrict__ bmod, const float* __restrict__ btgt,
    const float* __restrict__ ltau, const float* __restrict__ bvec,
    float* __restrict__ out)
{
    extern __shared__ char smem[];
    uint32_t sm = smem_u32(smem);
    int tid = threadIdx.x;
    int wid = tid >> 5, L = tid & 31;
    int wm = (wid & 1) * 64;          // warp m offset in CTA (2 warp-rows)
    int wn = (wid >> 1) * 32;         // warp n offset (4 warp-cols)
    int m0 = blockIdx.y * TM;
    int n0 = blockIdx.x * TN;

    // lane-invariant ldmatrix offsets
    uint32_t laneAoff = (uint32_t)((L & 15) * LDROW + (L >> 4) * 16);
    uint32_t laneBoff = (uint32_t)((((L >> 3) & 1) * 8 + (L & 7)) * LDROW + ((L >> 4) * 16));

    float acc[4][4][4];
#pragma unroll
    for (int a = 0; a < 4; a++)
#pragma unroll
        for (int b = 0; b < 4; b++)
#pragma unroll
            for (int c = 0; c < 4; c++) acc[a][b][c] = 0.f;

    // prologue: fill NSTAGE-1 stages
#pragma unroll
    for (int s = 0; s < NSTAGE - 1; s++) {
        load_stage(sm, s, s, m0, n0, tid);
        cp_commit();
    }

    for (int i = 0; i < ITERS; i++) {
        cp_wait<NSTAGE - 2>();
        __syncthreads();
        // refill stage written at iter i-1 (already consumed by all warps)
        int il = i + NSTAGE - 1;
        if (il < ITERS) load_stage(sm, il % NSTAGE, il, m0, n0, tid);
        cp_commit();

        int st = i % NSTAGE;
        uint32_t baseA = sm + st * STAGE_B + (uint32_t)wm * LDROW + laneAoff;
        uint32_t baseB = sm + st * STAGE_B + TILE_B + (uint32_t)wn * LDROW + laneBoff;
#pragma unroll
        for (int s = 0; s < 4; s++) {       // 4 x K16 per K64 chunk
            uint32_t a[4][4], b[2][4];
#pragma unroll
            for (int mi = 0; mi < 4; mi++)
                ldsm_x4(a[mi], baseA + mi * (16 * LDROW) + s * 32);
#pragma unroll
            for (int nj = 0; nj < 2; nj++)
                ldsm_x4(b[nj], baseB + nj * (16 * LDROW) + s * 32);
#pragma unroll
            for (int mi = 0; mi < 4; mi++)
#pragma unroll
                for (int ni = 0; ni < 4; ni++)
                    mma_16816(acc[mi][ni], a[mi], b[ni >> 1][ni & 1], b[ni >> 1][(ni & 1) + 2]);
        }
    }

    // ---- fused LTC epilogue straight from register accumulators ----
    // D frag: lane L, c0/c1 -> (m = L>>2, n = (L&3)*2 (+1)); c2/c3 -> m+8.
    int mb = m0 + wm + (L >> 2);
    int jc = (L & 3) * 2;
#pragma unroll
    for (int ni = 0; ni < 4; ni++) {
        int j = (n0 + wn + ni * 8 + jc) >> 1;    // even col = mod, odd = tgt
        float bm = bmod[j], bt = btgt[j];
        float tauv = expf(ltau[j]);
        float bv = bvec[j];
#pragma unroll
        for (int mi = 0; mi < 4; mi++) {
#pragma unroll
            for (int h2 = 0; h2 < 2; h2++) {
                int m = mb + mi * 16 + h2 * 8;
                float zm = acc[mi][ni][h2 * 2]     + bm;
                float zt = acc[mi][ni][h2 * 2 + 1] + bt;
                float f = tanhf(zm);
                float av = tanhf(zt);
                float tau_sys = tauv / (1.0f + tauv * fabsf(f));
                float decay = expf(-td[m] / (tau_sys + 1e-6f));
                float hv = hp[(size_t)m * HIDDEN + j];
                out[(size_t)m * HIDDEN + j] = decay * hv + (1.0f - decay) * (av + bv);
            }
        }
    }
}

// ---------------- host side --------------------------------------------------------
extern "C" void kernel_launch(void* const* d_in, const int* in_sizes, int n_in,
                              void* d_out, int out_size)
{
    const float* x    = (const float*)d_in[0];
    const float* h    = (const float*)d_in[1];
    const float* td   = (const float*)d_in[2];
    const float* Wmod = (const float*)d_in[3];
    const float* bmod = (const float*)d_in[4];
    const float* Wtgt = (const float*)d_in[5];
    const float* btgt = (const float*)d_in[6];
    const float* ltau = (const float*)d_in[7];
    const float* bias = (const float*)d_in[8];
    float* out = (float*)d_out;

    // 1) conversions
    {
        size_t n4 = (size_t)BATCH * FANIN / 4;
        build_A_kernel<<<(unsigned)((n4 + 255) / 256), 256>>>(x, h);
        dim3 gb(FANIN / 32, HIDDEN / 32, 2);
        build_B_kernel<<<gb, dim3(32, 8)>>>(Wmod, Wtgt);
    }

    // 2) fused 3-pass bf16-split GEMM + LTC epilogue
    static bool attr_set = false;
    if (!attr_set) {
        cudaFuncSetAttribute(ltc_gemm_kernel,
                             cudaFuncAttributeMaxDynamicSharedMemorySize, SMEM_BYTES);
        attr_set = true;
    }
    ltc_gemm_kernel<<<dim3(NTOT / TN, BATCH / TM), 256, SMEM_BYTES>>>(
        h, td, bmod, btgt, ltau, bias, out);
}

// round 5
// speedup vs baseline: 3.4398x; 3.4398x over previous
#include <cuda_runtime.h>
#include <cuda_fp16.h>
#include <cstdint>
#include <math.h>

#define BATCH   4096
#define INPUT   1024
#define HIDDEN  2048
#define FANIN   3072   // INPUT + HIDDEN
#define NTOT    4096   // 2 * HIDDEN (mod/tgt interleaved)

// ---------------- scratch (static device globals; no runtime allocation) ----------
static __device__ __half g_A[(size_t)BATCH * FANIN];
static __device__ __half g_B[(size_t)NTOT  * FANIN];

// ---------------- conversion kernels ----------------------------------------------
// A = [x | h] rows -> fp16, K-major [BATCH, FANIN].
__global__ void build_A_kernel(const float* __restrict__ xin, const float* __restrict__ hin) {
    size_t i = (size_t)blockIdx.x * blockDim.x + threadIdx.x;
    if (i >= (size_t)BATCH * FANIN / 4) return;
    size_t e = i * 4;
    int r = (int)(e / FANIN);
    int c = (int)(e % FANIN);
    float4 v = (c < INPUT)
        ? *(const float4*)(xin + (size_t)r * INPUT + c)
        : *(const float4*)(hin + (size_t)r * HIDDEN + (c - INPUT));
    __half2 lo = __floats2half2_rn(v.x, v.y);
    __half2 hi = __floats2half2_rn(v.z, v.w);
    *(uint32_t*)((__half*)g_A + e)     = *(uint32_t*)&lo;
    *(uint32_t*)((__half*)g_A + e + 2) = *(uint32_t*)&hi;
}

// B[n][k] = (n even ? W_mod : W_tgt)[k][n>>1] -> fp16. Transpose via SMEM tiles.
__global__ void build_B_kernel(const float* __restrict__ Wmod, const float* __restrict__ Wtgt) {
    __shared__ float tile[32][33];
    const float* W = blockIdx.z ? Wtgt : Wmod;
    int k0 = blockIdx.x * 32, j0 = blockIdx.y * 32;
    int tx = threadIdx.x, ty = threadIdx.y;   // 32 x 8
#pragma unroll
    for (int r = ty; r < 32; r += 8)
        tile[r][tx] = W[(size_t)(k0 + r) * HIDDEN + j0 + tx];
    __syncthreads();
#pragma unroll
    for (int jj = ty; jj < 32; jj += 8) {
        float v = tile[tx][jj];              // [k_local][j_local]
        int n = 2 * (j0 + jj) + blockIdx.z;  // interleave mod/tgt
        g_B[(size_t)n * FANIN + k0 + tx] = __float2half_rn(v);
    }
}

// ---------------- fused GEMM + LTC epilogue (mma.sync, SW128 swizzle) -------------
constexpr int TM = 128, TN = 128, KC = 64;
constexpr int NSTAGE = 3;
constexpr int ITERS  = FANIN / KC;            // 48 (single fp16 pass)
constexpr int TILE_B = 128 * 128;             // 16384 bytes (128 rows x 128B)
constexpr int STAGE_B = 2 * TILE_B;           // 32768
constexpr int SMEM_BYTES = NSTAGE * STAGE_B;  // 98304

__device__ __forceinline__ uint32_t smem_u32(const void* p) {
    uint32_t a;
    asm("{ .reg .u64 t; cvta.to.shared.u64 t, %1; cvt.u32.u64 %0, t; }" : "=r"(a) : "l"(p));
    return a;
}
__device__ __forceinline__ void cp_async16(uint32_t dst, const void* src) {
    asm volatile("cp.async.cg.shared.global [%0], [%1], 16;" :: "r"(dst), "l"(src));
}
__device__ __forceinline__ void cp_commit() {
    asm volatile("cp.async.commit_group;" ::: "memory");
}
template<int N> __device__ __forceinline__ void cp_wait() {
    asm volatile("cp.async.wait_group %0;" :: "n"(N) : "memory");
}
__device__ __forceinline__ void ldsm_x4(uint32_t* r, uint32_t addr) {
    asm volatile("ldmatrix.sync.aligned.m8n8.x4.shared.b16 {%0,%1,%2,%3}, [%4];"
                 : "=r"(r[0]), "=r"(r[1]), "=r"(r[2]), "=r"(r[3]) : "r"(addr));
}
__device__ __forceinline__ void mma_16816(float* c, const uint32_t* a, uint32_t b0, uint32_t b1) {
    asm volatile("mma.sync.aligned.m16n8k16.row.col.f32.f16.f16.f32 "
                 "{%0,%1,%2,%3}, {%4,%5,%6,%7}, {%8,%9}, {%0,%1,%2,%3};"
                 : "+f"(c[0]), "+f"(c[1]), "+f"(c[2]), "+f"(c[3])
                 : "r"(a[0]), "r"(a[1]), "r"(a[2]), "r"(a[3]), "r"(b0), "r"(b1));
}

// SW128: 16B chunk c within 128B row r stored at chunk (c ^ (r & 7)).
__device__ __forceinline__ void load_stage(uint32_t sm, int stage, int it,
                                           int m0, int n0, int tid)
{
    int k0 = it * KC;
    uint32_t sA = sm + stage * STAGE_B;
    uint32_t sB = sA + TILE_B;
#pragma unroll
    for (int i = 0; i < 4; i++) {             // A: 128 rows x 8 chunks / 256 thr
        int c = tid + i * 256;
        int row = c >> 3, c16 = c & 7;
        cp_async16(sA + row * 128 + ((c16 ^ (row & 7)) << 4),
                   g_A + (size_t)(m0 + row) * FANIN + k0 + c16 * 8);
    }
#pragma unroll
    for (int i = 0; i < 4; i++) {             // B: 128 rows x 8 chunks
        int c = tid + i * 256;
        int row = c >> 3, c16 = c & 7;
        cp_async16(sB + row * 128 + ((c16 ^ (row & 7)) << 4),
                   g_B + (size_t)(n0 + row) * FANIN + k0 + c16 * 8);
    }
}

__global__ void __launch_bounds__(256, 2) ltc_gemm_kernel(
    const float* __restrict__ hp, const float* __restrict__ td,
    const float* __restrict__ bmod, const float* __restrict__ btgt,
    const float* __restrict__ ltau, const float* __restrict__ bvec,
    float* __restrict__ out)
{
    extern __shared__ char smem[];
    uint32_t sm = smem_u32(smem);
    int tid = threadIdx.x;
    int wid = tid >> 5, L = tid & 31;
    int wm = (wid & 1) * 64;          // warp m offset (2 warp-rows)
    int wn = (wid >> 1) * 32;         // warp n offset (4 warp-cols)
    int m0 = blockIdx.y * TM;
    int n0 = blockIdx.x * TN;

    // ldmatrix lane rows + swizzle XOR keys (row low-3-bits invariant under +16*mi)
    uint32_t rA = (uint32_t)(wm + (L & 15));
    uint32_t rB = (uint32_t)(wn + ((L >> 3) & 1) * 8 + (L & 7));
    uint32_t xA = rA & 7, xB = rB & 7;
    uint32_t cbase = (uint32_t)(L >> 4);      // 0 or 1

    float acc[4][4][4];
#pragma unroll
    for (int a = 0; a < 4; a++)
#pragma unroll
        for (int b = 0; b < 4; b++)
#pragma unroll
            for (int c = 0; c < 4; c++) acc[a][b][c] = 0.f;

    // prologue: fill NSTAGE-1 stages
#pragma unroll
    for (int s = 0; s < NSTAGE - 1; s++) {
        load_stage(sm, s, s, m0, n0, tid);
        cp_commit();
    }

    for (int i = 0; i < ITERS; i++) {
        cp_wait<NSTAGE - 2>();
        __syncthreads();
        int il = i + NSTAGE - 1;
        if (il < ITERS) load_stage(sm, il % NSTAGE, il, m0, n0, tid);
        cp_commit();

        int st = i % NSTAGE;
        uint32_t baseA = sm + st * STAGE_B + rA * 128;
        uint32_t baseB = sm + st * STAGE_B + TILE_B + rB * 128;
#pragma unroll
        for (int s = 0; s < 4; s++) {       // 4 x K16 per K64 chunk
            uint32_t cA = ((s * 2 + cbase) ^ xA) << 4;
            uint32_t cB = ((s * 2 + cbase) ^ xB) << 4;
            uint32_t a[4][4], b[2][4];
#pragma unroll
            for (int mi = 0; mi < 4; mi++)
                ldsm_x4(a[mi], baseA + mi * (16 * 128) + cA);
#pragma unroll
            for (int nj = 0; nj < 2; nj++)
                ldsm_x4(b[nj], baseB + nj * (16 * 128) + cB);
#pragma unroll
            for (int mi = 0; mi < 4; mi++)
#pragma unroll
                for (int ni = 0; ni < 4; ni++)
                    mma_16816(acc[mi][ni], a[mi], b[ni >> 1][ni & 1], b[ni >> 1][(ni & 1) + 2]);
        }
    }

    // ---- fused LTC epilogue straight from register accumulators ----
    // D frag: lane L, c0/c1 -> (m = L>>2, n = (L&3)*2 (+1)); c2/c3 -> m+8.
    int mb = m0 + wm + (L >> 2);
    int jc = (L & 3) * 2;
#pragma unroll
    for (int ni = 0; ni < 4; ni++) {
        int j = (n0 + wn + ni * 8 + jc) >> 1;    // even col = mod, odd = tgt
        float bm = bmod[j], bt = btgt[j];
        float tauv = expf(ltau[j]);
        float bv = bvec[j];
#pragma unroll
        for (int mi = 0; mi < 4; mi++) {
#pragma unroll
            for (int h2 = 0; h2 < 2; h2++) {
                int m = mb + mi * 16 + h2 * 8;
                float zm = acc[mi][ni][h2 * 2]     + bm;
                float zt = acc[mi][ni][h2 * 2 + 1] + bt;
                float f = tanhf(zm);
                float av = tanhf(zt);
                float tau_sys = tauv / (1.0f + tauv * fabsf(f));
                float decay = expf(-td[m] / (tau_sys + 1e-6f));
                float hv = hp[(size_t)m * HIDDEN + j];
                out[(size_t)m * HIDDEN + j] = decay * hv + (1.0f - decay) * (av + bv);
            }
        }
    }
}

// ---------------- host side --------------------------------------------------------
extern "C" void kernel_launch(void* const* d_in, const int* in_sizes, int n_in,
                              void* d_out, int out_size)
{
    const float* x    = (const float*)d_in[0];
    const float* h    = (const float*)d_in[1];
    const float* td   = (const float*)d_in[2];
    const float* Wmod = (const float*)d_in[3];
    const float* bmod = (const float*)d_in[4];
    const float* Wtgt = (const float*)d_in[5];
    const float* btgt = (const float*)d_in[6];
    const float* ltau = (const float*)d_in[7];
    const float* bias = (const float*)d_in[8];
    float* out = (float*)d_out;

    // 1) conversions
    {
        size_t n4 = (size_t)BATCH * FANIN / 4;
        build_A_kernel<<<(unsigned)((n4 + 255) / 256), 256>>>(x, h);
        dim3 gb(FANIN / 32, HIDDEN / 32, 2);
        build_B_kernel<<<gb, dim3(32, 8)>>>(Wmod, Wtgt);
    }

    // 2) fused single-pass fp16 GEMM + LTC epilogue
    static bool attr_set = false;
    if (!attr_set) {
        cudaFuncSetAttribute(ltc_gemm_kernel,
                             cudaFuncAttributeMaxDynamicSharedMemorySize, SMEM_BYTES);
        attr_set = true;
    }
    ltc_gemm_kernel<<<dim3(NTOT / TN, BATCH / TM), 256, SMEM_BYTES>>>(
        h, td, bmod, btgt, ltau, bias, out);
}